// round 1
// baseline (speedup 1.0000x reference)
#include <cuda_runtime.h>
#include <math.h>

#define N_NODES 100000
#define N_EDGES 1600000
#define N_GRAPHS 64
#define EPSF 1e-7f

#define SCAN_B 1024
#define NB_SCAN ((N_NODES + SCAN_B - 1) / SCAN_B)   // 98

// ---------------- scratch (device globals, no allocation) ----------------
__device__ int   g_deg[N_NODES];
__device__ int   g_rowstart[N_NODES];
__device__ int   g_cursor[N_NODES];
__device__ int   g_csr_src[N_EDGES];
__device__ int   g_blocksums[128];
__device__ float g_buf0[(size_t)N_NODES * 192];
__device__ float g_buf1[(size_t)N_NODES * 192];
__device__ float g_pool_sum[N_GRAPHS * 128];
__device__ int   g_pool_cnt[N_GRAPHS];

__device__ __forceinline__ float* bufsel(int i) { return i == 0 ? g_buf0 : g_buf1; }

// ---------------- CSR build ----------------
__global__ void k_zero() {
    int i = blockIdx.x * blockDim.x + threadIdx.x;
    if (i < N_NODES) g_deg[i] = 0;
    if (i < N_GRAPHS * 128) g_pool_sum[i] = 0.f;
    if (i < N_GRAPHS) g_pool_cnt[i] = 0;
}

__global__ void k_hist(const int* __restrict__ dst) {
    int i = blockIdx.x * blockDim.x + threadIdx.x;
    if (i < N_EDGES) atomicAdd(&g_deg[dst[i]], 1);
}

__global__ void k_scan1() {
    int idx = blockIdx.x * SCAN_B + threadIdx.x;
    int v = (idx < N_NODES) ? g_deg[idx] : 0;
    int lane = threadIdx.x & 31, w = threadIdx.x >> 5;
    int x = v;
    #pragma unroll
    for (int o = 1; o < 32; o <<= 1) {
        int t = __shfl_up_sync(0xffffffffu, x, o);
        if (lane >= o) x += t;
    }
    __shared__ int wsum[32];
    if (lane == 31) wsum[w] = x;
    __syncthreads();
    if (w == 0) {
        int y = wsum[lane];
        #pragma unroll
        for (int o = 1; o < 32; o <<= 1) {
            int t = __shfl_up_sync(0xffffffffu, y, o);
            if (lane >= o) y += t;
        }
        wsum[lane] = y;
    }
    __syncthreads();
    int incl = x + (w > 0 ? wsum[w - 1] : 0);
    if (idx < N_NODES) g_rowstart[idx] = incl - v;     // block-local exclusive
    if (threadIdx.x == SCAN_B - 1) g_blocksums[blockIdx.x] = incl;
}

__global__ void k_scan2() {
    int t = threadIdx.x;                                // 128 threads, NB_SCAN=98
    int v = (t < NB_SCAN) ? g_blocksums[t] : 0;
    int lane = t & 31, w = t >> 5;
    int x = v;
    #pragma unroll
    for (int o = 1; o < 32; o <<= 1) {
        int tt = __shfl_up_sync(0xffffffffu, x, o);
        if (lane >= o) x += tt;
    }
    __shared__ int ws[4];
    if (lane == 31) ws[w] = x;
    __syncthreads();
    if (t == 0) {
        int a = 0;
        #pragma unroll
        for (int i = 0; i < 4; i++) { int tmp = ws[i]; ws[i] = a; a += tmp; }
    }
    __syncthreads();
    int incl = x + ws[w];
    if (t < 128) g_blocksums[t] = incl - v;             // exclusive
}

__global__ void k_scan3() {
    int idx = blockIdx.x * SCAN_B + threadIdx.x;
    if (idx < N_NODES) {
        int r = g_rowstart[idx] + g_blocksums[idx >> 10];
        g_rowstart[idx] = r;
        g_cursor[idx] = r;
    }
}

__global__ void k_fill(const int* __restrict__ src, const int* __restrict__ dst) {
    int i = blockIdx.x * blockDim.x + threadIdx.x;
    if (i < N_EDGES) {
        int p = atomicAdd(&g_cursor[dst[i]], 1);
        g_csr_src[p] = src[i];
    }
}

// ---------------- aggregation: y = x + segsum(relu(x[src])) + deg*eps ----------------
// one warp per node; lane covers D/32 features
template <int D>
__global__ void k_agg(const float* __restrict__ xext, int inbuf, int outbuf) {
    int gw = (blockIdx.x * blockDim.x + threadIdx.x) >> 5;
    if (gw >= N_NODES) return;
    int lane = threadIdx.x & 31;
    const float* X = xext ? xext : bufsel(inbuf);
    float* Y = bufsel(outbuf);

    constexpr int NF = D / 32;
    float acc[NF];
    #pragma unroll
    for (int i = 0; i < NF; i++) acc[i] = 0.f;

    int start = g_rowstart[gw];
    int deg = g_deg[gw];

    for (int base = 0; base < deg; base += 32) {
        int myidx = (base + lane < deg) ? g_csr_src[start + base + lane] : 0;
        int cnt = min(32, deg - base);
        for (int e = 0; e < cnt; e++) {
            int s = __shfl_sync(0xffffffffu, myidx, e);
            const float* row = X + (size_t)s * D;
            #pragma unroll
            for (int i = 0; i < NF; i++) {
                float v = __ldg(row + lane + i * 32);
                acc[i] += fmaxf(v, 0.f);
            }
        }
    }

    const float* xr = X + (size_t)gw * D;
    float* yr = Y + (size_t)gw * D;
    float ep = (float)deg * EPSF;
    #pragma unroll
    for (int i = 0; i < NF; i++)
        yr[lane + i * 32] = xr[lane + i * 32] + acc[i] + ep;
}

// ---------------- GEMM: C[N,DO] = Y[N,K] @ W[K,DO] + b ----------------
// BM=128, BN=64, BK=16, 256 threads, 8x4 per thread
template <int K, int DO>
__global__ __launch_bounds__(256) void k_gemm(int inbuf, int outbuf,
                                              const float* __restrict__ W,
                                              const float* __restrict__ b) {
    const float* Y = bufsel(inbuf);
    float* C = bufsel(outbuf);

    __shared__ float As[16][128];
    __shared__ float Bs[16][64];

    int tid = threadIdx.x;
    int bm = blockIdx.x * 128;
    int bn = blockIdx.y * 64;
    int tx = tid & 15, ty = tid >> 4;

    float acc[8][4];
    #pragma unroll
    for (int i = 0; i < 8; i++)
        #pragma unroll
        for (int j = 0; j < 4; j++) acc[i][j] = 0.f;

    for (int kt = 0; kt < K; kt += 16) {
        // A tile: 128x16 = 512 float4 loads, transposed into As[k][row]
        #pragma unroll
        for (int l = 0; l < 2; l++) {
            int v = tid + l * 256;
            int row = v >> 2;
            int k4 = (v & 3) * 4;
            int grow = bm + row;
            float4 a = make_float4(0.f, 0.f, 0.f, 0.f);
            if (grow < N_NODES)
                a = *(const float4*)(Y + (size_t)grow * K + kt + k4);
            As[k4 + 0][row] = a.x;
            As[k4 + 1][row] = a.y;
            As[k4 + 2][row] = a.z;
            As[k4 + 3][row] = a.w;
        }
        // B tile: 16x64 = 256 float4
        {
            int row = tid >> 4;
            int c4 = (tid & 15) * 4;
            float4 w = *(const float4*)(W + (size_t)(kt + row) * DO + bn + c4);
            *(float4*)&Bs[row][c4] = w;
        }
        __syncthreads();

        #pragma unroll
        for (int k = 0; k < 16; k++) {
            float rb[4], ra[8];
            #pragma unroll
            for (int j = 0; j < 4; j++) rb[j] = Bs[k][tx * 4 + j];
            #pragma unroll
            for (int i = 0; i < 8; i++) ra[i] = As[k][ty * 8 + i];
            #pragma unroll
            for (int i = 0; i < 8; i++)
                #pragma unroll
                for (int j = 0; j < 4; j++) acc[i][j] += ra[i] * rb[j];
        }
        __syncthreads();
    }

    #pragma unroll
    for (int i = 0; i < 8; i++) {
        int grow = bm + ty * 8 + i;
        if (grow < N_NODES) {
            #pragma unroll
            for (int j = 0; j < 4; j++) {
                int col = bn + tx * 4 + j;
                C[(size_t)grow * DO + col] = acc[i][j] + b[col];
            }
        }
    }
}

// ---------------- pooling ----------------
__global__ void k_pool_accum(const int* __restrict__ batch) {
    const float* H = g_buf1;                        // final layer output, d=128
    __shared__ float s_sum[N_GRAPHS * 128];
    __shared__ int s_cnt[N_GRAPHS];
    for (int i = threadIdx.x; i < N_GRAPHS * 128; i += blockDim.x) s_sum[i] = 0.f;
    for (int i = threadIdx.x; i < N_GRAPHS; i += blockDim.x) s_cnt[i] = 0;
    __syncthreads();

    int lane = threadIdx.x & 31;
    int warps = (gridDim.x * blockDim.x) >> 5;
    for (int n = (blockIdx.x * blockDim.x + threadIdx.x) >> 5; n < N_NODES; n += warps) {
        int g = batch[n];
        #pragma unroll
        for (int i = 0; i < 4; i++)
            atomicAdd(&s_sum[g * 128 + lane + i * 32], H[(size_t)n * 128 + lane + i * 32]);
        if (lane == 0) atomicAdd(&s_cnt[g], 1);
    }
    __syncthreads();
    for (int i = threadIdx.x; i < N_GRAPHS * 128; i += blockDim.x)
        atomicAdd(&g_pool_sum[i], s_sum[i]);
    for (int i = threadIdx.x; i < N_GRAPHS; i += blockDim.x)
        atomicAdd(&g_pool_cnt[i], s_cnt[i]);
}

__global__ void k_head(const float* __restrict__ Wfc, const float* __restrict__ bfc,
                       float* __restrict__ out) {
    __shared__ float s_logit[N_GRAPHS][10];
    __shared__ float s_lse[N_GRAPHS];
    int tid = threadIdx.x;                           // 640 threads
    int g = tid / 10, j = tid % 10;
    float cnt = fmaxf((float)g_pool_cnt[g], 1.f);
    float acc = bfc[j];
    #pragma unroll 8
    for (int f = 0; f < 128; f++)
        acc += (g_pool_sum[g * 128 + f] / cnt) * Wfc[f * 10 + j];
    s_logit[g][j] = acc;
    __syncthreads();
    if (j == 0) {
        float m = -1e30f;
        #pragma unroll
        for (int t = 0; t < 10; t++) m = fmaxf(m, s_logit[g][t]);
        float s = 0.f;
        #pragma unroll
        for (int t = 0; t < 10; t++) s += expf(s_logit[g][t] - m);
        s_lse[g] = m + logf(s);
    }
    __syncthreads();
    out[g * 10 + j] = s_logit[g][j] - s_lse[g];
}

// ---------------- launch ----------------
extern "C" void kernel_launch(void* const* d_in, const int* in_sizes, int n_in,
                              void* d_out, int out_size) {
    const float* x   = (const float*)d_in[0];
    const float* W0  = (const float*)d_in[1];
    const float* b0  = (const float*)d_in[2];
    const float* W1  = (const float*)d_in[3];
    const float* b1  = (const float*)d_in[4];
    const float* W2  = (const float*)d_in[5];
    const float* b2  = (const float*)d_in[6];
    const float* W3  = (const float*)d_in[7];
    const float* b3  = (const float*)d_in[8];
    const float* Wfc = (const float*)d_in[9];
    const float* bfc = (const float*)d_in[10];
    const int* ei    = (const int*)d_in[11];
    const int* batch = (const int*)d_in[12];
    const int* src = ei;
    const int* dst = ei + N_EDGES;
    float* out = (float*)d_out;

    // CSR build
    k_zero<<<(N_NODES + 255) / 256, 256>>>();
    k_hist<<<(N_EDGES + 255) / 256, 256>>>(dst);
    k_scan1<<<NB_SCAN, SCAN_B>>>();
    k_scan2<<<1, 128>>>();
    k_scan3<<<NB_SCAN, SCAN_B>>>();
    k_fill<<<(N_EDGES + 255) / 256, 256>>>(src, dst);

    int agg_blocks = (N_NODES * 32 + 255) / 256;
    dim3 g1((N_NODES + 127) / 128, 192 / 64);
    dim3 g2((N_NODES + 127) / 128, 192 / 64);
    dim3 g4((N_NODES + 127) / 128, 128 / 64);

    // layer 1: x(ext,128) -> buf0 -> gemm(128,192) -> buf1
    k_agg<128><<<agg_blocks, 256>>>(x, 0, 0);
    k_gemm<128, 192><<<g1, 256>>>(0, 1, W0, b0);
    // layer 2: buf1(192) -> buf0 -> gemm(192,192) -> buf1
    k_agg<192><<<agg_blocks, 256>>>(nullptr, 1, 0);
    k_gemm<192, 192><<<g2, 256>>>(0, 1, W1, b1);
    // layer 3
    k_agg<192><<<agg_blocks, 256>>>(nullptr, 1, 0);
    k_gemm<192, 192><<<g2, 256>>>(0, 1, W2, b2);
    // layer 4: buf1(192) -> buf0 -> gemm(192,128) -> buf1
    k_agg<192><<<agg_blocks, 256>>>(nullptr, 1, 0);
    k_gemm<192, 128><<<g4, 256>>>(0, 1, W3, b3);

    // pooling + head
    k_pool_accum<<<296, 256>>>(batch);
    k_head<<<1, 640>>>(Wfc, bfc, out);
}

// round 4
// speedup vs baseline: 1.2414x; 1.2414x over previous
#include <cuda_runtime.h>
#include <cuda_bf16.h>
#include <math.h>
#include <stdint.h>

#define N_NODES 100000
#define N_EDGES 1600000
#define N_GRAPHS 64
#define EPSF 1e-7f

#define SCAN_B 1024
#define NB_SCAN ((N_NODES + SCAN_B - 1) / SCAN_B)   // 98

// ---------------- scratch (device globals, device-side access ONLY) --------
__device__ int   g_deg[N_NODES];
__device__ int   g_rowstart[N_NODES];
__device__ int   g_cursor[N_NODES];
__device__ int   g_csr_src[N_EDGES];
__device__ int   g_blocksums[128];
// fp32 GEMM output (layer i) -> input of next agg; final layer -> pool
__device__ __align__(16) float g_bufC[(size_t)N_NODES * 192];
// split-bf16 activations (GEMM A operand), row stride = layer K
__device__ __align__(16) __nv_bfloat16 g_a1[(size_t)N_NODES * 192];
__device__ __align__(16) __nv_bfloat16 g_a2[(size_t)N_NODES * 192];
// split-bf16 transposed weights [DO][K]
__device__ __align__(16) __nv_bfloat16 g_w1t[192 * 192];
__device__ __align__(16) __nv_bfloat16 g_w2t[192 * 192];
__device__ float g_pool_sum[N_GRAPHS * 128];
__device__ int   g_pool_cnt[N_GRAPHS];

__device__ __forceinline__ uint32_t packbf(float a, float b) {
    __nv_bfloat162 t = __floats2bfloat162_rn(a, b);
    return *(uint32_t*)&t;
}

// ---------------- CSR build ----------------
__global__ void k_zero() {
    int i = blockIdx.x * blockDim.x + threadIdx.x;
    if (i < N_NODES) g_deg[i] = 0;
    if (i < N_GRAPHS * 128) g_pool_sum[i] = 0.f;
    if (i < N_GRAPHS) g_pool_cnt[i] = 0;
}

__global__ void k_hist(const int* __restrict__ dst) {
    int i = blockIdx.x * blockDim.x + threadIdx.x;
    if (i < N_EDGES) atomicAdd(&g_deg[dst[i]], 1);
}

__global__ void k_scan1() {
    int idx = blockIdx.x * SCAN_B + threadIdx.x;
    int v = (idx < N_NODES) ? g_deg[idx] : 0;
    int lane = threadIdx.x & 31, w = threadIdx.x >> 5;
    int x = v;
    #pragma unroll
    for (int o = 1; o < 32; o <<= 1) {
        int t = __shfl_up_sync(0xffffffffu, x, o);
        if (lane >= o) x += t;
    }
    __shared__ int wsum[32];
    if (lane == 31) wsum[w] = x;
    __syncthreads();
    if (w == 0) {
        int y = wsum[lane];
        #pragma unroll
        for (int o = 1; o < 32; o <<= 1) {
            int t = __shfl_up_sync(0xffffffffu, y, o);
            if (lane >= o) y += t;
        }
        wsum[lane] = y;
    }
    __syncthreads();
    int incl = x + (w > 0 ? wsum[w - 1] : 0);
    if (idx < N_NODES) g_rowstart[idx] = incl - v;
    if (threadIdx.x == SCAN_B - 1) g_blocksums[blockIdx.x] = incl;
}

__global__ void k_scan2() {
    int t = threadIdx.x;
    int v = (t < NB_SCAN) ? g_blocksums[t] : 0;
    int lane = t & 31, w = t >> 5;
    int x = v;
    #pragma unroll
    for (int o = 1; o < 32; o <<= 1) {
        int tt = __shfl_up_sync(0xffffffffu, x, o);
        if (lane >= o) x += tt;
    }
    __shared__ int ws[4];
    if (lane == 31) ws[w] = x;
    __syncthreads();
    if (t == 0) {
        int a = 0;
        #pragma unroll
        for (int i = 0; i < 4; i++) { int tmp = ws[i]; ws[i] = a; a += tmp; }
    }
    __syncthreads();
    int incl = x + ws[w];
    if (t < 128) g_blocksums[t] = incl - v;
}

__global__ void k_scan3() {
    int idx = blockIdx.x * SCAN_B + threadIdx.x;
    if (idx < N_NODES) {
        int r = g_rowstart[idx] + g_blocksums[idx >> 10];
        g_rowstart[idx] = r;
        g_cursor[idx] = r;
    }
}

__global__ void k_fill(const int* __restrict__ src, const int* __restrict__ dst) {
    int i = blockIdx.x * blockDim.x + threadIdx.x;
    if (i < N_EDGES) {
        int p = atomicAdd(&g_cursor[dst[i]], 1);
        g_csr_src[p] = src[i];
    }
}

// ---------------- aggregation: y = x + segsum(relu(x[src])) + deg*eps ------
// one warp/node, float4 gather; emits split-bf16 (hi to g_a1, lo to g_a2)
// X source: xext if non-null (layer 1), else g_bufC (device global).
template <int D>
__global__ void k_agg(const float* __restrict__ xext) {
    int gw = (blockIdx.x * blockDim.x + threadIdx.x) >> 5;
    if (gw >= N_NODES) return;
    int lane = threadIdx.x & 31;
    constexpr int NC = D / 4;

    const float* X = xext ? xext : (const float*)g_bufC;

    float4 a0 = make_float4(0.f, 0.f, 0.f, 0.f);
    float4 a1 = make_float4(0.f, 0.f, 0.f, 0.f);

    int start = g_rowstart[gw];
    int deg = g_deg[gw];
    const float4* Xv = (const float4*)X;

    for (int base = 0; base < deg; base += 32) {
        int myidx = (base + lane < deg) ? g_csr_src[start + base + lane] : 0;
        int cnt = min(32, deg - base);
        for (int e = 0; e < cnt; e++) {
            int s = __shfl_sync(0xffffffffu, myidx, e);
            const float4* row = Xv + (size_t)s * NC;
            float4 v = __ldg(row + lane);
            a0.x += fmaxf(v.x, 0.f); a0.y += fmaxf(v.y, 0.f);
            a0.z += fmaxf(v.z, 0.f); a0.w += fmaxf(v.w, 0.f);
            if (D == 192 && lane < 16) {
                float4 w = __ldg(row + 32 + lane);
                a1.x += fmaxf(w.x, 0.f); a1.y += fmaxf(w.y, 0.f);
                a1.z += fmaxf(w.z, 0.f); a1.w += fmaxf(w.w, 0.f);
            }
        }
    }

    const float4* xr = Xv + (size_t)gw * NC;
    float ep = (float)deg * EPSF;

    float4 xv = __ldg(xr + lane);
    float y0 = xv.x + a0.x + ep, y1 = xv.y + a0.y + ep;
    float y2 = xv.z + a0.z + ep, y3 = xv.w + a0.w + ep;
    {
        uint32_t h0 = packbf(y0, y1), h1 = packbf(y2, y3);
        __nv_bfloat162 hh0 = *(__nv_bfloat162*)&h0, hh1 = *(__nv_bfloat162*)&h1;
        float2 f0 = __bfloat1622float2(hh0), f1 = __bfloat1622float2(hh1);
        uint32_t l0 = packbf(y0 - f0.x, y1 - f0.y), l1 = packbf(y2 - f1.x, y3 - f1.y);
        size_t off = (size_t)gw * D + lane * 4;
        *(uint2*)((char*)g_a1 + off * 2) = make_uint2(h0, h1);
        *(uint2*)((char*)g_a2 + off * 2) = make_uint2(l0, l1);
    }
    if (D == 192 && lane < 16) {
        float4 xw = __ldg(xr + 32 + lane);
        float z0 = xw.x + a1.x + ep, z1 = xw.y + a1.y + ep;
        float z2 = xw.z + a1.z + ep, z3 = xw.w + a1.w + ep;
        uint32_t h0 = packbf(z0, z1), h1 = packbf(z2, z3);
        __nv_bfloat162 hh0 = *(__nv_bfloat162*)&h0, hh1 = *(__nv_bfloat162*)&h1;
        float2 f0 = __bfloat1622float2(hh0), f1 = __bfloat1622float2(hh1);
        uint32_t l0 = packbf(z0 - f0.x, z1 - f0.y), l1 = packbf(z2 - f1.x, z3 - f1.y);
        size_t off = (size_t)gw * D + 128 + lane * 4;
        *(uint2*)((char*)g_a1 + off * 2) = make_uint2(h0, h1);
        *(uint2*)((char*)g_a2 + off * 2) = make_uint2(l0, l1);
    }
}

// ---------------- weight prep: W[K,DO] f32 -> split bf16 [DO][K] -----------
__global__ void k_wprep(const float* __restrict__ W, int K, int DO) {
    int i = blockIdx.x * blockDim.x + threadIdx.x;
    if (i < K * DO) {
        int k = i / DO, n = i % DO;
        float w = W[i];
        __nv_bfloat16 h = __float2bfloat16(w);
        float r = w - __bfloat162float(h);
        g_w1t[n * K + k] = h;
        g_w2t[n * K + k] = __float2bfloat16(r);
    }
}

// ---------------- HMMA GEMM: g_bufC[N,DO] = (A1+A2)[N,K] @ Wt + b ----------
// mma.sync m16n8k16 bf16, split x3. CTA 128x64, 8 warps (4Mx2N), warp 32x32.
#define MMA_BF16(d, a, b0_, b1_) \
    asm volatile("mma.sync.aligned.m16n8k16.row.col.f32.bf16.bf16.f32 " \
        "{%0,%1,%2,%3}, {%4,%5,%6,%7}, {%8,%9}, {%0,%1,%2,%3};" \
        : "+f"((d)[0]), "+f"((d)[1]), "+f"((d)[2]), "+f"((d)[3]) \
        : "r"((a)[0]), "r"((a)[1]), "r"((a)[2]), "r"((a)[3]), \
          "r"(b0_), "r"(b1_))

template <int K, int DO>
__global__ __launch_bounds__(256) void k_gemm(const float* __restrict__ bias) {
    float* C = g_bufC;
    // 80-byte row stride: fragment LDS bank phase (20g+t)%32 conflict-free
    __shared__ char As1[128 * 80];
    __shared__ char As2[128 * 80];
    __shared__ char Bs1[64 * 80];
    __shared__ char Bs2[64 * 80];

    int tid = threadIdx.x;
    int lane = tid & 31, wid = tid >> 5;
    int g = lane >> 2, t = lane & 3;
    int wm = wid & 3, wn = wid >> 2;
    int bm = blockIdx.x * 128;
    int bn = blockIdx.y * 64;

    float acc[2][4][4];
    #pragma unroll
    for (int i = 0; i < 2; i++)
        #pragma unroll
        for (int j = 0; j < 4; j++)
            #pragma unroll
            for (int q = 0; q < 4; q++) acc[i][j][q] = 0.f;

    constexpr int NCHUNK = K / 32;
    for (int c = 0; c < NCHUNK; c++) {
        // A tiles: 128 rows x 32 bf16 (64B) per split
        #pragma unroll
        for (int i = 0; i < 2; i++) {
            int slot = tid * 2 + i;
            int row = slot >> 2, ch = slot & 3;
            int grow = bm + row;
            uint4 v1 = make_uint4(0, 0, 0, 0), v2 = v1;
            if (grow < N_NODES) {
                size_t gb = ((size_t)grow * K + c * 32) * 2 + ch * 16;
                v1 = __ldg((const uint4*)((const char*)g_a1 + gb));
                v2 = __ldg((const uint4*)((const char*)g_a2 + gb));
            }
            *(uint4*)(As1 + row * 80 + ch * 16) = v1;
            *(uint4*)(As2 + row * 80 + ch * 16) = v2;
        }
        // B tiles: 64 rows x 32 bf16 per split
        {
            int n = tid >> 2, ch = tid & 3;
            size_t gb = ((size_t)(bn + n) * K + c * 32) * 2 + ch * 16;
            *(uint4*)(Bs1 + n * 80 + ch * 16) = __ldg((const uint4*)((const char*)g_w1t + gb));
            *(uint4*)(Bs2 + n * 80 + ch * 16) = __ldg((const uint4*)((const char*)g_w2t + gb));
        }
        __syncthreads();

        #pragma unroll
        for (int ks = 0; ks < 2; ks++) {
            int kb = ks * 32;   // byte offset within row (16 bf16)
            uint32_t a1f[2][4], a2f[2][4];
            #pragma unroll
            for (int mt = 0; mt < 2; mt++) {
                int rb = (wm * 32 + mt * 16 + g) * 80 + kb + t * 4;
                a1f[mt][0] = *(const uint32_t*)(As1 + rb);
                a1f[mt][1] = *(const uint32_t*)(As1 + rb + 8 * 80);
                a1f[mt][2] = *(const uint32_t*)(As1 + rb + 16);
                a1f[mt][3] = *(const uint32_t*)(As1 + rb + 8 * 80 + 16);
                a2f[mt][0] = *(const uint32_t*)(As2 + rb);
                a2f[mt][1] = *(const uint32_t*)(As2 + rb + 8 * 80);
                a2f[mt][2] = *(const uint32_t*)(As2 + rb + 16);
                a2f[mt][3] = *(const uint32_t*)(As2 + rb + 8 * 80 + 16);
            }
            #pragma unroll
            for (int nt = 0; nt < 4; nt++) {
                int nb = (wn * 32 + nt * 8 + g) * 80 + kb + t * 4;
                uint32_t b10 = *(const uint32_t*)(Bs1 + nb);
                uint32_t b11 = *(const uint32_t*)(Bs1 + nb + 16);
                uint32_t b20 = *(const uint32_t*)(Bs2 + nb);
                uint32_t b21 = *(const uint32_t*)(Bs2 + nb + 16);
                #pragma unroll
                for (int mt = 0; mt < 2; mt++) {
                    MMA_BF16(acc[mt][nt], a1f[mt], b10, b11);
                    MMA_BF16(acc[mt][nt], a1f[mt], b20, b21);
                    MMA_BF16(acc[mt][nt], a2f[mt], b10, b11);
                }
            }
        }
        __syncthreads();
    }

    // epilogue
    #pragma unroll
    for (int nt = 0; nt < 4; nt++) {
        int col = bn + wn * 32 + nt * 8 + 2 * t;
        float2 bv = *(const float2*)(bias + col);
        #pragma unroll
        for (int mt = 0; mt < 2; mt++) {
            int r0 = bm + wm * 32 + mt * 16 + g;
            if (r0 < N_NODES) {
                float2 o = make_float2(acc[mt][nt][0] + bv.x, acc[mt][nt][1] + bv.y);
                *(float2*)(C + (size_t)r0 * DO + col) = o;
            }
            int r1 = r0 + 8;
            if (r1 < N_NODES) {
                float2 o = make_float2(acc[mt][nt][2] + bv.x, acc[mt][nt][3] + bv.y);
                *(float2*)(C + (size_t)r1 * DO + col) = o;
            }
        }
    }
}

// ---------------- pooling ----------------
__global__ void k_pool_accum(const int* __restrict__ batch) {
    const float* H = g_bufC;                        // final layer output, d=128
    __shared__ float s_sum[N_GRAPHS * 128];
    __shared__ int s_cnt[N_GRAPHS];
    for (int i = threadIdx.x; i < N_GRAPHS * 128; i += blockDim.x) s_sum[i] = 0.f;
    for (int i = threadIdx.x; i < N_GRAPHS; i += blockDim.x) s_cnt[i] = 0;
    __syncthreads();

    int lane = threadIdx.x & 31;
    int warps = (gridDim.x * blockDim.x) >> 5;
    for (int n = (blockIdx.x * blockDim.x + threadIdx.x) >> 5; n < N_NODES; n += warps) {
        int g = batch[n];
        #pragma unroll
        for (int i = 0; i < 4; i++)
            atomicAdd(&s_sum[g * 128 + lane + i * 32], H[(size_t)n * 128 + lane + i * 32]);
        if (lane == 0) atomicAdd(&s_cnt[g], 1);
    }
    __syncthreads();
    for (int i = threadIdx.x; i < N_GRAPHS * 128; i += blockDim.x)
        atomicAdd(&g_pool_sum[i], s_sum[i]);
    for (int i = threadIdx.x; i < N_GRAPHS; i += blockDim.x)
        atomicAdd(&g_pool_cnt[i], s_cnt[i]);
}

__global__ void k_head(const float* __restrict__ Wfc, const float* __restrict__ bfc,
                       float* __restrict__ out) {
    __shared__ float s_logit[N_GRAPHS][10];
    __shared__ float s_lse[N_GRAPHS];
    int tid = threadIdx.x;                           // 640 threads
    int g = tid / 10, j = tid % 10;
    float cnt = fmaxf((float)g_pool_cnt[g], 1.f);
    float acc = bfc[j];
    #pragma unroll 8
    for (int f = 0; f < 128; f++)
        acc += (g_pool_sum[g * 128 + f] / cnt) * Wfc[f * 10 + j];
    s_logit[g][j] = acc;
    __syncthreads();
    if (j == 0) {
        float m = -1e30f;
        #pragma unroll
        for (int t = 0; t < 10; t++) m = fmaxf(m, s_logit[g][t]);
        float s = 0.f;
        #pragma unroll
        for (int t = 0; t < 10; t++) s += expf(s_logit[g][t] - m);
        s_lse[g] = m + logf(s);
    }
    __syncthreads();
    out[g * 10 + j] = s_logit[g][j] - s_lse[g];
}

// ---------------- launch ----------------
extern "C" void kernel_launch(void* const* d_in, const int* in_sizes, int n_in,
                              void* d_out, int out_size) {
    const float* x   = (const float*)d_in[0];
    const float* W0  = (const float*)d_in[1];
    const float* b0  = (const float*)d_in[2];
    const float* W1  = (const float*)d_in[3];
    const float* b1  = (const float*)d_in[4];
    const float* W2  = (const float*)d_in[5];
    const float* b2  = (const float*)d_in[6];
    const float* W3  = (const float*)d_in[7];
    const float* b3  = (const float*)d_in[8];
    const float* Wfc = (const float*)d_in[9];
    const float* bfc = (const float*)d_in[10];
    const int* ei    = (const int*)d_in[11];
    const int* batch = (const int*)d_in[12];
    const int* src = ei;
    const int* dst = ei + N_EDGES;
    float* out = (float*)d_out;

    // CSR build
    k_zero<<<(N_NODES + 255) / 256, 256>>>();
    k_hist<<<(N_EDGES + 255) / 256, 256>>>(dst);
    k_scan1<<<NB_SCAN, SCAN_B>>>();
    k_scan2<<<1, 128>>>();
    k_scan3<<<NB_SCAN, SCAN_B>>>();
    k_fill<<<(N_EDGES + 255) / 256, 256>>>(src, dst);

    int agg_blocks = (N_NODES * 32 + 255) / 256;
    dim3 g192((N_NODES + 127) / 128, 3);
    dim3 g128((N_NODES + 127) / 128, 2);

    // layer 1: x(128) -> agg(split bf16) -> gemm(128->192) -> g_bufC
    k_wprep<<<(128 * 192 + 255) / 256, 256>>>(W0, 128, 192);
    k_agg<128><<<agg_blocks, 256>>>(x);
    k_gemm<128, 192><<<g192, 256>>>(b0);
    // layer 2
    k_wprep<<<(192 * 192 + 255) / 256, 256>>>(W1, 192, 192);
    k_agg<192><<<agg_blocks, 256>>>(nullptr);
    k_gemm<192, 192><<<g192, 256>>>(b1);
    // layer 3
    k_wprep<<<(192 * 192 + 255) / 256, 256>>>(W2, 192, 192);
    k_agg<192><<<agg_blocks, 256>>>(nullptr);
    k_gemm<192, 192><<<g192, 256>>>(b2);
    // layer 4
    k_wprep<<<(192 * 128 + 255) / 256, 256>>>(W3, 192, 128);
    k_agg<192><<<agg_blocks, 256>>>(nullptr);
    k_gemm<192, 128><<<g128, 256>>>(b3);

    // pooling + head
    k_pool_accum<<<296, 256>>>(batch);
    k_head<<<1, 640>>>(Wfc, bfc, out);
}